// round 2
// baseline (speedup 1.0000x reference)
#include <cuda_runtime.h>
#include <cstdint>

#define BATCH 4
#define NVIS 4096
#define NLAN 256
#define VD 1024
#define LD 768
#define EMB 1024
#define NH 16
#define HD 64
#define SCALE_F 0.25f

// ---------------- scratch (device globals: allocation-free) ----------------
__device__ float g_Qp[(size_t)BATCH * NVIS * EMB];   // 64 MB  [B,Nv,E]
__device__ float g_Kp[(size_t)BATCH * NLAN * EMB];   //  4 MB  [B,Nl,E]
__device__ float g_Vv[(size_t)BATCH * NVIS * EMB];   // 64 MB
__device__ float g_Vl[(size_t)BATCH * NLAN * EMB];   //  4 MB
__device__ float g_Ov[(size_t)BATCH * NVIS * EMB];   // 64 MB  pre-proj out_v
__device__ float g_Ol[(size_t)BATCH * NLAN * EMB];   //  4 MB  pre-proj out_l
__device__ float g_S [(size_t)BATCH * NH * NVIS * NLAN]; // 268 MB scaled scores
__device__ float g_cmax[BATCH * NH * NLAN];
__device__ float g_cinv[BATCH * NH * NLAN];

// ---------------- generic SGEMM: C[M,N] = A[M,K] @ W[K,N] + bias ----------
// 128x128 block, BK=8, 256 threads, 8x8 microtile. Requires M%128==0,
// N%128==0, K%8==0 (all shapes here satisfy this).
__global__ __launch_bounds__(256) void sgemm_bias(
    const float* __restrict__ A, const float* __restrict__ W,
    const float* __restrict__ bias, float* __restrict__ C,
    int M, int N, int K)
{
    __shared__ float As[8][128];
    __shared__ float Ws[8][128];
    const int tid = threadIdx.x;
    const int tx = tid & 15, ty = tid >> 4;
    const int arow = tid >> 1, acol = (tid & 1) * 4;
    const int wrow = tid >> 5, wcol = (tid & 31) * 4;
    const float* Ab = A + (size_t)blockIdx.y * 128 * K;
    const float* Wb = W + blockIdx.x * 128;

    float acc[8][8];
#pragma unroll
    for (int i = 0; i < 8; i++)
#pragma unroll
        for (int j = 0; j < 8; j++) acc[i][j] = 0.f;

    for (int k0 = 0; k0 < K; k0 += 8) {
        float4 av = *(const float4*)(Ab + (size_t)arow * K + k0 + acol);
        As[acol + 0][arow] = av.x;
        As[acol + 1][arow] = av.y;
        As[acol + 2][arow] = av.z;
        As[acol + 3][arow] = av.w;
        *(float4*)&Ws[wrow][wcol] =
            *(const float4*)(Wb + (size_t)(k0 + wrow) * N + wcol);
        __syncthreads();
#pragma unroll
        for (int k = 0; k < 8; k++) {
            float ra[8], rb[8];
            *(float4*)&ra[0] = *(const float4*)&As[k][ty * 8];
            *(float4*)&ra[4] = *(const float4*)&As[k][ty * 8 + 4];
            *(float4*)&rb[0] = *(const float4*)&Ws[k][tx * 8];
            *(float4*)&rb[4] = *(const float4*)&Ws[k][tx * 8 + 4];
#pragma unroll
            for (int i = 0; i < 8; i++)
#pragma unroll
                for (int j = 0; j < 8; j++)
                    acc[i][j] = fmaf(ra[i], rb[j], acc[i][j]);
        }
        __syncthreads();
    }

    const int cn = blockIdx.x * 128 + tx * 8;
    float bi[8];
    *(float4*)&bi[0] = *(const float4*)&bias[cn];
    *(float4*)&bi[4] = *(const float4*)&bias[cn + 4];
#pragma unroll
    for (int i = 0; i < 8; i++) {
        float* Crow = C + (size_t)(blockIdx.y * 128 + ty * 8 + i) * N + cn;
        float4 o0 = make_float4(acc[i][0] + bi[0], acc[i][1] + bi[1],
                                acc[i][2] + bi[2], acc[i][3] + bi[3]);
        float4 o1 = make_float4(acc[i][4] + bi[4], acc[i][5] + bi[5],
                                acc[i][6] + bi[6], acc[i][7] + bi[7]);
        *(float4*)Crow = o0;
        *(float4*)(Crow + 4) = o1;
    }
}

// ---------------- fused vision-attends-language -------------------------
// grid (Nv/64, H, B), 256 threads. For a 64-row Q tile:
//   S = scale * Q K^T  (full Nl=256 keys in smem)  -> g_S (unmasked, for
//   the column softmax), + mask bias -> smem; row softmax; P @ Vl -> g_Ov.
#define SM_QS 0                       // Qs[64][64]  (reused as Vl chunk)
#define SM_KS (64 * 64)               // Ks[256][68]
#define SM_SS (SM_KS + 256 * 68)      // Ss[64][256]
#define SM_MK (SM_SS + 64 * 256)      // mask[256] (as float storage of int)
#define SMEM_FLOATS (SM_MK + 256)

__global__ __launch_bounds__(256) void attn_v_fused(const int* __restrict__ maskL)
{
    extern __shared__ float sm[];
    float* Qs = sm + SM_QS;
    float* Ks = sm + SM_KS;
    float* Ss = sm + SM_SS;
    int*   mk = (int*)(sm + SM_MK);

    const int tid = threadIdx.x;
    const int tx = tid & 15, ty = tid >> 4;
    const int b = blockIdx.z, h = blockIdx.y;
    const int q0 = blockIdx.x * 64;

    const float* Qg = g_Qp + (size_t)b * NVIS * EMB + h * HD;
    const float* Kg = g_Kp + (size_t)b * NLAN * EMB + h * HD;
    const float* Vg = g_Vl + (size_t)b * NLAN * EMB + h * HD;

    // load Q tile 64x64
#pragma unroll
    for (int it = 0; it < 4; it++) {
        int id = tid + it * 256;
        int r = id >> 4, c4 = (id & 15) * 4;
        *(float4*)&Qs[r * 64 + c4] =
            *(const float4*)&Qg[(size_t)(q0 + r) * EMB + c4];
    }
    // load K 256x64 (row-major, padded stride 68)
#pragma unroll
    for (int it = 0; it < 16; it++) {
        int id = tid + it * 256;
        int n = id >> 4, c4 = (id & 15) * 4;
        *(float4*)&Ks[n * 68 + c4] =
            *(const float4*)&Kg[(size_t)n * EMB + c4];
    }
    mk[tid] = maskL[b * NLAN + tid];
    __syncthreads();

    // S = Q K^T : each thread owns 4 q-rows x 16 j-cols (j = tx + 16*jj)
    float s[4][16];
#pragma unroll
    for (int i = 0; i < 4; i++)
#pragma unroll
        for (int j = 0; j < 16; j++) s[i][j] = 0.f;

    for (int d = 0; d < 64; d++) {
        float ra[4], rb[16];
#pragma unroll
        for (int i = 0; i < 4; i++) ra[i] = Qs[(ty * 4 + i) * 64 + d];
#pragma unroll
        for (int j = 0; j < 16; j++) rb[j] = Ks[(tx + 16 * j) * 68 + d];
#pragma unroll
        for (int i = 0; i < 4; i++)
#pragma unroll
            for (int j = 0; j < 16; j++)
                s[i][j] = fmaf(ra[i], rb[j], s[i][j]);
    }

    // scale; store raw to g_S; masked to smem
    float* Sg = g_S + ((size_t)(b * NH + h) * NVIS + q0) * NLAN;
#pragma unroll
    for (int i = 0; i < 4; i++) {
        int qi = ty * 4 + i;
#pragma unroll
        for (int j = 0; j < 16; j++) {
            int jc = tx + 16 * j;
            float v = s[i][j] * SCALE_F;
            Sg[(size_t)qi * NLAN + jc] = v;
            Ss[qi * 256 + jc] = v + (mk[jc] ? 0.f : -1e9f);
        }
    }
    __syncthreads();

    // row softmax: warp w owns rows w*8 .. w*8+7
    {
        const int w = tid >> 5, lane = tid & 31;
#pragma unroll
        for (int r = 0; r < 8; r++) {
            float* row = Ss + (w * 8 + r) * 256;
            float x[8], m = -1e30f;
#pragma unroll
            for (int e = 0; e < 8; e++) { x[e] = row[lane + 32 * e]; m = fmaxf(m, x[e]); }
#pragma unroll
            for (int off = 16; off; off >>= 1)
                m = fmaxf(m, __shfl_xor_sync(0xffffffffu, m, off));
            float sum = 0.f;
#pragma unroll
            for (int e = 0; e < 8; e++) { x[e] = __expf(x[e] - m); sum += x[e]; }
#pragma unroll
            for (int off = 16; off; off >>= 1)
                sum += __shfl_xor_sync(0xffffffffu, sum, off);
            float inv = 1.f / sum;
#pragma unroll
            for (int e = 0; e < 8; e++) row[lane + 32 * e] = x[e] * inv;
        }
    }
    __syncthreads();

    // O = P @ Vl : thread owns 4 q x 4 d, stream Vl in 64-row chunks into Qs
    float o[4][4];
#pragma unroll
    for (int i = 0; i < 4; i++)
#pragma unroll
        for (int j = 0; j < 4; j++) o[i][j] = 0.f;

    for (int jc = 0; jc < 4; jc++) {
#pragma unroll
        for (int it = 0; it < 4; it++) {
            int id = tid + it * 256;
            int r = id >> 4, c4 = (id & 15) * 4;
            *(float4*)&Qs[r * 64 + c4] =
                *(const float4*)&Vg[(size_t)(jc * 64 + r) * EMB + c4];
        }
        __syncthreads();
#pragma unroll 4
        for (int jl = 0; jl < 64; jl++) {
            int j = jc * 64 + jl;
            float ra[4];
#pragma unroll
            for (int i = 0; i < 4; i++) ra[i] = Ss[(ty * 4 + i) * 256 + j];
            float4 rb = *(const float4*)&Qs[jl * 64 + tx * 4];
#pragma unroll
            for (int i = 0; i < 4; i++) {
                o[i][0] = fmaf(ra[i], rb.x, o[i][0]);
                o[i][1] = fmaf(ra[i], rb.y, o[i][1]);
                o[i][2] = fmaf(ra[i], rb.z, o[i][2]);
                o[i][3] = fmaf(ra[i], rb.w, o[i][3]);
            }
        }
        __syncthreads();
    }

#pragma unroll
    for (int i = 0; i < 4; i++) {
        float4 ov = make_float4(o[i][0], o[i][1], o[i][2], o[i][3]);
        *(float4*)&g_Ov[(size_t)(b * NVIS + q0 + ty * 4 + i) * EMB + h * HD + tx * 4] = ov;
    }
}

// ---------------- column stats for language-attends-vision ---------------
// grid = B*H blocks, 256 threads; thread k reduces over Nv for its column.
__global__ __launch_bounds__(256) void col_stats()
{
    const int bh = blockIdx.x;
    const int k = threadIdx.x;
    const float* Sc = g_S + (size_t)bh * NVIS * NLAN + k;
    float m = -1e30f;
#pragma unroll 8
    for (int q = 0; q < NVIS; q++) m = fmaxf(m, Sc[(size_t)q * NLAN]);
    float sum = 0.f;
#pragma unroll 8
    for (int q = 0; q < NVIS; q++) sum += __expf(Sc[(size_t)q * NLAN] - m);
    g_cmax[bh * NLAN + k] = m;
    g_cinv[bh * NLAN + k] = 1.f / sum;
}

// ---------------- out_l = attn_l^T @ Vv ----------------------------------
// grid (Nl/64, H, B), 256 threads; thread owns 4 k x 4 d.
__global__ __launch_bounds__(256) void attn_l_out()
{
    __shared__ float Wsm[64][68];   // normalized weights chunk [q][k]
    __shared__ float Vs[64][64];    // Vv chunk [q][d]
    __shared__ float ms[64], is_[64];

    const int tid = threadIdx.x;
    const int tx = tid & 15, ty = tid >> 4;
    const int b = blockIdx.z, h = blockIdx.y, k0 = blockIdx.x * 64;
    const int bh = b * NH + h;

    if (tid < 64) {
        ms[tid] = g_cmax[bh * NLAN + k0 + tid];
        is_[tid] = g_cinv[bh * NLAN + k0 + tid];
    }
    __syncthreads();

    float acc[4][4];
#pragma unroll
    for (int i = 0; i < 4; i++)
#pragma unroll
        for (int j = 0; j < 4; j++) acc[i][j] = 0.f;

    const float* Sg = g_S + (size_t)bh * NVIS * NLAN;
    const float* Vg = g_Vv + (size_t)b * NVIS * EMB + h * HD;

    for (int qc = 0; qc < NVIS / 64; qc++) {
#pragma unroll
        for (int it = 0; it < 4; it++) {
            int id = tid + it * 256;
            int q = id >> 4, k4 = (id & 15) * 4;
            float4 v = *(const float4*)&Sg[(size_t)(qc * 64 + q) * NLAN + k0 + k4];
            Wsm[q][k4 + 0] = __expf(v.x - ms[k4 + 0]) * is_[k4 + 0];
            Wsm[q][k4 + 1] = __expf(v.y - ms[k4 + 1]) * is_[k4 + 1];
            Wsm[q][k4 + 2] = __expf(v.z - ms[k4 + 2]) * is_[k4 + 2];
            Wsm[q][k4 + 3] = __expf(v.w - ms[k4 + 3]) * is_[k4 + 3];
        }
#pragma unroll
        for (int it = 0; it < 4; it++) {
            int id = tid + it * 256;
            int q = id >> 4, c4 = (id & 15) * 4;
            *(float4*)&Vs[q][c4] =
                *(const float4*)&Vg[(size_t)(qc * 64 + q) * EMB + c4];
        }
        __syncthreads();
#pragma unroll 4
        for (int q = 0; q < 64; q++) {
            float ra[4];
#pragma unroll
            for (int i = 0; i < 4; i++) ra[i] = Wsm[q][ty * 4 + i];
            float4 rb = *(const float4*)&Vs[q][tx * 4];
#pragma unroll
            for (int i = 0; i < 4; i++) {
                acc[i][0] = fmaf(ra[i], rb.x, acc[i][0]);
                acc[i][1] = fmaf(ra[i], rb.y, acc[i][1]);
                acc[i][2] = fmaf(ra[i], rb.z, acc[i][2]);
                acc[i][3] = fmaf(ra[i], rb.w, acc[i][3]);
            }
        }
        __syncthreads();
    }

#pragma unroll
    for (int i = 0; i < 4; i++) {
        float4 ov = make_float4(acc[i][0], acc[i][1], acc[i][2], acc[i][3]);
        *(float4*)&g_Ol[(size_t)(b * NLAN + k0 + ty * 4 + i) * EMB + h * HD + tx * 4] = ov;
    }
}

// -------------------------------------------------------------------------
extern "C" void kernel_launch(void* const* d_in, const int* in_sizes, int n_in,
                              void* d_out, int out_size)
{
    (void)in_sizes; (void)n_in; (void)out_size;
    const float* v    = (const float*)d_in[0];
    const float* l    = (const float*)d_in[1];
    const int*   mask = (const int*)d_in[2];
    const float* Wv2q = (const float*)d_in[3];  const float* bv2q = (const float*)d_in[4];
    const float* Wl2k = (const float*)d_in[5];  const float* bl2k = (const float*)d_in[6];
    const float* Wv2v = (const float*)d_in[7];  const float* bv2v = (const float*)d_in[8];
    const float* Wl2v = (const float*)d_in[9];  const float* bl2v = (const float*)d_in[10];
    const float* Wv2o = (const float*)d_in[11]; const float* bv2o = (const float*)d_in[12];
    const float* Wl2o = (const float*)d_in[13]; const float* bl2o = (const float*)d_in[14];

    float* outv = (float*)d_out;                               // [B,Nv,VD]
    float* outl = outv + (size_t)BATCH * NVIS * VD;            // [B,Nl,LD]

    float *Qp, *Kp, *Vv, *Vl, *Ov, *Ol;
    cudaGetSymbolAddress((void**)&Qp, g_Qp);
    cudaGetSymbolAddress((void**)&Kp, g_Kp);
    cudaGetSymbolAddress((void**)&Vv, g_Vv);
    cudaGetSymbolAddress((void**)&Vl, g_Vl);
    cudaGetSymbolAddress((void**)&Ov, g_Ov);
    cudaGetSymbolAddress((void**)&Ol, g_Ol);

    const int smem_bytes = SMEM_FLOATS * 4;
    cudaFuncSetAttribute(attn_v_fused,
                         cudaFuncAttributeMaxDynamicSharedMemorySize, smem_bytes);

    // 1-4: input projections
    sgemm_bias<<<dim3(EMB / 128, BATCH * NVIS / 128), 256>>>(v, Wv2q, bv2q, Qp,
                                                             BATCH * NVIS, EMB, VD);
    sgemm_bias<<<dim3(EMB / 128, BATCH * NLAN / 128), 256>>>(l, Wl2k, bl2k, Kp,
                                                             BATCH * NLAN, EMB, LD);
    sgemm_bias<<<dim3(EMB / 128, BATCH * NVIS / 128), 256>>>(v, Wv2v, bv2v, Vv,
                                                             BATCH * NVIS, EMB, VD);
    sgemm_bias<<<dim3(EMB / 128, BATCH * NLAN / 128), 256>>>(l, Wl2v, bl2v, Vl,
                                                             BATCH * NLAN, EMB, LD);

    // 5: fused S + row-softmax + P@Vl (writes g_S and g_Ov)
    attn_v_fused<<<dim3(NVIS / 64, NH, BATCH), 256, smem_bytes>>>(mask);

    // 6-7: column softmax stats + out_l accumulation
    col_stats<<<BATCH * NH, 256>>>();
    attn_l_out<<<dim3(NLAN / 64, NH, BATCH), 256>>>();

    // 8-9: output projections straight into d_out
    sgemm_bias<<<dim3(VD / 128, BATCH * NVIS / 128), 256>>>(Ov, Wv2o, bv2o, outv,
                                                            BATCH * NVIS, VD, EMB);
    sgemm_bias<<<dim3(LD / 128, BATCH * NLAN / 128), 256>>>(Ol, Wl2o, bl2o, outl,
                                                            BATCH * NLAN, LD, EMB);
}

// round 5
// speedup vs baseline: 1.7496x; 1.7496x over previous
#include <cuda_runtime.h>
#include <cstdint>

#define BATCH 4
#define NVIS 4096
#define NLAN 256
#define VD 1024
#define LD 768
#define EMB 1024
#define NH 16
#define HD 64
#define SCALE_F 0.25f

// ---------------- scratch (device globals: allocation-free) ----------------
__device__ float g_Qp[(size_t)BATCH * NVIS * EMB];   // 64 MB  [B,Nv,E]
__device__ float g_Kp[(size_t)BATCH * NLAN * EMB];   //  4 MB  [B,Nl,E]
__device__ float g_Vv[(size_t)BATCH * NVIS * EMB];   // 64 MB
__device__ float g_Vl[(size_t)BATCH * NLAN * EMB];   //  4 MB
__device__ float g_Ov[(size_t)BATCH * NVIS * EMB];   // 64 MB  pre-proj out_v
__device__ float g_Ol[(size_t)BATCH * NLAN * EMB];   //  4 MB  pre-proj out_l
__device__ float g_S [(size_t)BATCH * NH * NVIS * NLAN]; // 268 MB scaled scores
__device__ float g_cmax[BATCH * NH * NLAN];
__device__ float g_cinv[BATCH * NH * NLAN];

__device__ __forceinline__ unsigned f2tf32(float x) {
    unsigned r;
    asm("cvt.rna.tf32.f32 %0, %1;" : "=r"(r) : "f"(x));
    return r;
}

// ---------------- tf32 tensor-core GEMM: C = A[M,K] @ W[K,N] + bias -------
// 128x128 block, BK=32, 256 threads (8 warps, 2x4), warp tile 64x32,
// mma.sync m16n8k8 tf32. Requires M%128==0, N%128==0, K%32==0.
#define AST 133   // As stride: conflict-free transpose stores, 2-way frag loads
#define BST 132   // Bs stride: float4-aligned, 2-way frag loads

__global__ __launch_bounds__(256) void gemm_tf32_bias(
    const float* __restrict__ A, const float* __restrict__ W,
    const float* __restrict__ bias, float* __restrict__ C,
    int M, int N, int K)
{
    __shared__ unsigned As[32 * AST];   // [k][m]
    __shared__ unsigned Bs[32 * BST];   // [k][n]

    const int tid = threadIdx.x;
    const int lane = tid & 31, wid = tid >> 5;
    const int wm = wid >> 2, wn = wid & 3;     // warp grid 2(m) x 4(n)
    const int bm = blockIdx.y * 128, bn = blockIdx.x * 128;
    const int lk = lane & 3, lr = lane >> 2;

    float acc[4][4][4] = {};

    for (int k0 = 0; k0 < K; k0 += 32) {
        // A tile 128x32 -> As[k][m] (transpose, tf32-rounded)
#pragma unroll
        for (int i = 0; i < 4; i++) {
            int f = tid + i * 256;
            int row = f >> 3, k4 = (f & 7) * 4;
            float4 v = *(const float4*)(A + (size_t)(bm + row) * K + k0 + k4);
            As[(k4 + 0) * AST + row] = f2tf32(v.x);
            As[(k4 + 1) * AST + row] = f2tf32(v.y);
            As[(k4 + 2) * AST + row] = f2tf32(v.z);
            As[(k4 + 3) * AST + row] = f2tf32(v.w);
        }
        // B tile 32x128 -> Bs[k][n]
#pragma unroll
        for (int i = 0; i < 4; i++) {
            int f = tid + i * 256;
            int kr = f >> 5, n4 = (f & 31) * 4;
            float4 v = *(const float4*)(W + (size_t)(k0 + kr) * N + bn + n4);
            uint4 u = make_uint4(f2tf32(v.x), f2tf32(v.y), f2tf32(v.z), f2tf32(v.w));
            *(uint4*)&Bs[kr * BST + n4] = u;
        }
        __syncthreads();

#pragma unroll
        for (int ks = 0; ks < 4; ks++) {
            const int k = ks * 8;
            unsigned af[4][4], bf[4][2];
#pragma unroll
            for (int mt = 0; mt < 4; mt++) {
                int mr = wm * 64 + mt * 16 + lr;
                af[mt][0] = As[(k + lk) * AST + mr];
                af[mt][1] = As[(k + lk) * AST + mr + 8];
                af[mt][2] = As[(k + 4 + lk) * AST + mr];
                af[mt][3] = As[(k + 4 + lk) * AST + mr + 8];
            }
#pragma unroll
            for (int nt = 0; nt < 4; nt++) {
                int nc = wn * 32 + nt * 8 + lr;
                bf[nt][0] = Bs[(k + lk) * BST + nc];
                bf[nt][1] = Bs[(k + 4 + lk) * BST + nc];
            }
#pragma unroll
            for (int mt = 0; mt < 4; mt++)
#pragma unroll
                for (int nt = 0; nt < 4; nt++)
                    asm volatile(
                        "mma.sync.aligned.m16n8k8.row.col.f32.tf32.tf32.f32 "
                        "{%0,%1,%2,%3}, {%4,%5,%6,%7}, {%8,%9}, {%0,%1,%2,%3};"
                        : "+f"(acc[mt][nt][0]), "+f"(acc[mt][nt][1]),
                          "+f"(acc[mt][nt][2]), "+f"(acc[mt][nt][3])
                        : "r"(af[mt][0]), "r"(af[mt][1]),
                          "r"(af[mt][2]), "r"(af[mt][3]),
                          "r"(bf[nt][0]), "r"(bf[nt][1]));
        }
        __syncthreads();
    }

    // epilogue: bias + store (c0,c1 at row r, cols c,c+1; c2,c3 at row r+8)
#pragma unroll
    for (int mt = 0; mt < 4; mt++) {
        int r0 = bm + wm * 64 + mt * 16 + lr;
#pragma unroll
        for (int nt = 0; nt < 4; nt++) {
            int c = bn + wn * 32 + nt * 8 + lk * 2;
            float2 b2 = *(const float2*)(bias + c);
            float2 o0 = make_float2(acc[mt][nt][0] + b2.x, acc[mt][nt][1] + b2.y);
            float2 o1 = make_float2(acc[mt][nt][2] + b2.x, acc[mt][nt][3] + b2.y);
            *(float2*)(C + (size_t)r0 * N + c) = o0;
            *(float2*)(C + (size_t)(r0 + 8) * N + c) = o1;
        }
    }
}

// ---------------- fused vision-attends-language -------------------------
// grid (Nv/64, H, B), 256 threads. For a 64-row Q tile:
//   S = scale * Q K^T  (full Nl=256 keys in smem)  -> g_S (unmasked, for
//   the column softmax), + mask bias -> smem; row softmax; P @ Vl -> g_Ov.
#define SM_QS 0                       // Qs[64][64]  (reused as Vl chunk)
#define SM_KS (64 * 64)               // Ks[256][68]
#define SM_SS (SM_KS + 256 * 68)      // Ss[64][256]
#define SM_MK (SM_SS + 64 * 256)      // mask[256]
#define SMEM_FLOATS (SM_MK + 256)

__global__ __launch_bounds__(256) void attn_v_fused(const int* __restrict__ maskL)
{
    extern __shared__ float sm[];
    float* Qs = sm + SM_QS;
    float* Ks = sm + SM_KS;
    float* Ss = sm + SM_SS;
    int*   mk = (int*)(sm + SM_MK);

    const int tid = threadIdx.x;
    const int tx = tid & 15, ty = tid >> 4;
    const int b = blockIdx.z, h = blockIdx.y;
    const int q0 = blockIdx.x * 64;

    const float* Qg = g_Qp + (size_t)b * NVIS * EMB + h * HD;
    const float* Kg = g_Kp + (size_t)b * NLAN * EMB + h * HD;
    const float* Vg = g_Vl + (size_t)b * NLAN * EMB + h * HD;

#pragma unroll
    for (int it = 0; it < 4; it++) {
        int id = tid + it * 256;
        int r = id >> 4, c4 = (id & 15) * 4;
        *(float4*)&Qs[r * 64 + c4] =
            *(const float4*)&Qg[(size_t)(q0 + r) * EMB + c4];
    }
#pragma unroll
    for (int it = 0; it < 16; it++) {
        int id = tid + it * 256;
        int n = id >> 4, c4 = (id & 15) * 4;
        *(float4*)&Ks[n * 68 + c4] =
            *(const float4*)&Kg[(size_t)n * EMB + c4];
    }
    mk[tid] = maskL[b * NLAN + tid];
    __syncthreads();

    float s[4][16];
#pragma unroll
    for (int i = 0; i < 4; i++)
#pragma unroll
        for (int j = 0; j < 16; j++) s[i][j] = 0.f;

    for (int d = 0; d < 64; d++) {
        float ra[4], rb[16];
#pragma unroll
        for (int i = 0; i < 4; i++) ra[i] = Qs[(ty * 4 + i) * 64 + d];
#pragma unroll
        for (int j = 0; j < 16; j++) rb[j] = Ks[(tx + 16 * j) * 68 + d];
#pragma unroll
        for (int i = 0; i < 4; i++)
#pragma unroll
            for (int j = 0; j < 16; j++)
                s[i][j] = fmaf(ra[i], rb[j], s[i][j]);
    }

    float* Sg = g_S + ((size_t)(b * NH + h) * NVIS + q0) * NLAN;
#pragma unroll
    for (int i = 0; i < 4; i++) {
        int qi = ty * 4 + i;
#pragma unroll
        for (int j = 0; j < 16; j++) {
            int jc = tx + 16 * j;
            float v = s[i][j] * SCALE_F;
            Sg[(size_t)qi * NLAN + jc] = v;
            Ss[qi * 256 + jc] = v + (mk[jc] ? 0.f : -1e9f);
        }
    }
    __syncthreads();

    {
        const int w = tid >> 5, lane = tid & 31;
#pragma unroll
        for (int r = 0; r < 8; r++) {
            float* row = Ss + (w * 8 + r) * 256;
            float x[8], m = -1e30f;
#pragma unroll
            for (int e = 0; e < 8; e++) { x[e] = row[lane + 32 * e]; m = fmaxf(m, x[e]); }
#pragma unroll
            for (int off = 16; off; off >>= 1)
                m = fmaxf(m, __shfl_xor_sync(0xffffffffu, m, off));
            float sum = 0.f;
#pragma unroll
            for (int e = 0; e < 8; e++) { x[e] = __expf(x[e] - m); sum += x[e]; }
#pragma unroll
            for (int off = 16; off; off >>= 1)
                sum += __shfl_xor_sync(0xffffffffu, sum, off);
            float inv = 1.f / sum;
#pragma unroll
            for (int e = 0; e < 8; e++) row[lane + 32 * e] = x[e] * inv;
        }
    }
    __syncthreads();

    float o[4][4];
#pragma unroll
    for (int i = 0; i < 4; i++)
#pragma unroll
        for (int j = 0; j < 4; j++) o[i][j] = 0.f;

    for (int jc = 0; jc < 4; jc++) {
#pragma unroll
        for (int it = 0; it < 4; it++) {
            int id = tid + it * 256;
            int r = id >> 4, c4 = (id & 15) * 4;
            *(float4*)&Qs[r * 64 + c4] =
                *(const float4*)&Vg[(size_t)(jc * 64 + r) * EMB + c4];
        }
        __syncthreads();
#pragma unroll 4
        for (int jl = 0; jl < 64; jl++) {
            int j = jc * 64 + jl;
            float ra[4];
#pragma unroll
            for (int i = 0; i < 4; i++) ra[i] = Ss[(ty * 4 + i) * 256 + j];
            float4 rb = *(const float4*)&Qs[jl * 64 + tx * 4];
#pragma unroll
            for (int i = 0; i < 4; i++) {
                o[i][0] = fmaf(ra[i], rb.x, o[i][0]);
                o[i][1] = fmaf(ra[i], rb.y, o[i][1]);
                o[i][2] = fmaf(ra[i], rb.z, o[i][2]);
                o[i][3] = fmaf(ra[i], rb.w, o[i][3]);
            }
        }
        __syncthreads();
    }

#pragma unroll
    for (int i = 0; i < 4; i++) {
        float4 ov = make_float4(o[i][0], o[i][1], o[i][2], o[i][3]);
        *(float4*)&g_Ov[(size_t)(b * NVIS + q0 + ty * 4 + i) * EMB + h * HD + tx * 4] = ov;
    }
}

// ---------------- column stats for language-attends-vision ---------------
__global__ __launch_bounds__(256) void col_stats()
{
    const int bh = blockIdx.x;
    const int k = threadIdx.x;
    const float* Sc = g_S + (size_t)bh * NVIS * NLAN + k;
    float m = -1e30f;
#pragma unroll 8
    for (int q = 0; q < NVIS; q++) m = fmaxf(m, Sc[(size_t)q * NLAN]);
    float sum = 0.f;
#pragma unroll 8
    for (int q = 0; q < NVIS; q++) sum += __expf(Sc[(size_t)q * NLAN] - m);
    g_cmax[bh * NLAN + k] = m;
    g_cinv[bh * NLAN + k] = 1.f / sum;
}

// ---------------- out_l = attn_l^T @ Vv ----------------------------------
__global__ __launch_bounds__(256) void attn_l_out()
{
    __shared__ float Wsm[64][68];
    __shared__ float Vs[64][64];
    __shared__ float ms[64], is_[64];

    const int tid = threadIdx.x;
    const int tx = tid & 15, ty = tid >> 4;
    const int b = blockIdx.z, h = blockIdx.y, k0 = blockIdx.x * 64;
    const int bh = b * NH + h;

    if (tid < 64) {
        ms[tid] = g_cmax[bh * NLAN + k0 + tid];
        is_[tid] = g_cinv[bh * NLAN + k0 + tid];
    }
    __syncthreads();

    float acc[4][4];
#pragma unroll
    for (int i = 0; i < 4; i++)
#pragma unroll
        for (int j = 0; j < 4; j++) acc[i][j] = 0.f;

    const float* Sg = g_S + (size_t)bh * NVIS * NLAN;
    const float* Vg = g_Vv + (size_t)b * NVIS * EMB + h * HD;

    for (int qc = 0; qc < NVIS / 64; qc++) {
#pragma unroll
        for (int it = 0; it < 4; it++) {
            int id = tid + it * 256;
            int q = id >> 4, k4 = (id & 15) * 4;
            float4 v = *(const float4*)&Sg[(size_t)(qc * 64 + q) * NLAN + k0 + k4];
            Wsm[q][k4 + 0] = __expf(v.x - ms[k4 + 0]) * is_[k4 + 0];
            Wsm[q][k4 + 1] = __expf(v.y - ms[k4 + 1]) * is_[k4 + 1];
            Wsm[q][k4 + 2] = __expf(v.z - ms[k4 + 2]) * is_[k4 + 2];
            Wsm[q][k4 + 3] = __expf(v.w - ms[k4 + 3]) * is_[k4 + 3];
        }
#pragma unroll
        for (int it = 0; it < 4; it++) {
            int id = tid + it * 256;
            int q = id >> 4, c4 = (id & 15) * 4;
            *(float4*)&Vs[q][c4] =
                *(const float4*)&Vg[(size_t)(qc * 64 + q) * EMB + c4];
        }
        __syncthreads();
#pragma unroll 4
        for (int q = 0; q < 64; q++) {
            float ra[4];
#pragma unroll
            for (int i = 0; i < 4; i++) ra[i] = Wsm[q][ty * 4 + i];
            float4 rb = *(const float4*)&Vs[q][tx * 4];
#pragma unroll
            for (int i = 0; i < 4; i++) {
                acc[i][0] = fmaf(ra[i], rb.x, acc[i][0]);
                acc[i][1] = fmaf(ra[i], rb.y, acc[i][1]);
                acc[i][2] = fmaf(ra[i], rb.z, acc[i][2]);
                acc[i][3] = fmaf(ra[i], rb.w, acc[i][3]);
            }
        }
        __syncthreads();
    }

#pragma unroll
    for (int i = 0; i < 4; i++) {
        float4 ov = make_float4(acc[i][0], acc[i][1], acc[i][2], acc[i][3]);
        *(float4*)&g_Ol[(size_t)(b * NLAN + k0 + ty * 4 + i) * EMB + h * HD + tx * 4] = ov;
    }
}

// -------------------------------------------------------------------------
extern "C" void kernel_launch(void* const* d_in, const int* in_sizes, int n_in,
                              void* d_out, int out_size)
{
    (void)in_sizes; (void)n_in; (void)out_size;
    const float* v    = (const float*)d_in[0];
    const float* l    = (const float*)d_in[1];
    const int*   mask = (const int*)d_in[2];
    const float* Wv2q = (const float*)d_in[3];  const float* bv2q = (const float*)d_in[4];
    const float* Wl2k = (const float*)d_in[5];  const float* bl2k = (const float*)d_in[6];
    const float* Wv2v = (const float*)d_in[7];  const float* bv2v = (const float*)d_in[8];
    const float* Wl2v = (const float*)d_in[9];  const float* bl2v = (const float*)d_in[10];
    const float* Wv2o = (const float*)d_in[11]; const float* bv2o = (const float*)d_in[12];
    const float* Wl2o = (const float*)d_in[13]; const float* bl2o = (const float*)d_in[14];

    float* outv = (float*)d_out;                               // [B,Nv,VD]
    float* outl = outv + (size_t)BATCH * NVIS * VD;            // [B,Nl,LD]

    float *Qp, *Kp, *Vv, *Vl, *Ov, *Ol;
    cudaGetSymbolAddress((void**)&Qp, g_Qp);
    cudaGetSymbolAddress((void**)&Kp, g_Kp);
    cudaGetSymbolAddress((void**)&Vv, g_Vv);
    cudaGetSymbolAddress((void**)&Vl, g_Vl);
    cudaGetSymbolAddress((void**)&Ov, g_Ov);
    cudaGetSymbolAddress((void**)&Ol, g_Ol);

    const int smem_bytes = SMEM_FLOATS * 4;
    cudaFuncSetAttribute(attn_v_fused,
                         cudaFuncAttributeMaxDynamicSharedMemorySize, smem_bytes);

    // 1-4: input projections (tf32 tensor cores)
    gemm_tf32_bias<<<dim3(EMB / 128, BATCH * NVIS / 128), 256>>>(v, Wv2q, bv2q, Qp,
                                                                 BATCH * NVIS, EMB, VD);
    gemm_tf32_bias<<<dim3(EMB / 128, BATCH * NLAN / 128), 256>>>(l, Wl2k, bl2k, Kp,
                                                                 BATCH * NLAN, EMB, LD);
    gemm_tf32_bias<<<dim3(EMB / 128, BATCH * NVIS / 128), 256>>>(v, Wv2v, bv2v, Vv,
                                                                 BATCH * NVIS, EMB, VD);
    gemm_tf32_bias<<<dim3(EMB / 128, BATCH * NLAN / 128), 256>>>(l, Wl2v, bl2v, Vl,
                                                                 BATCH * NLAN, EMB, LD);

    // 5: fused S + row-softmax + P@Vl (writes g_S and g_Ov)
    attn_v_fused<<<dim3(NVIS / 64, NH, BATCH), 256, smem_bytes>>>(mask);

    // 6-7: column softmax stats + out_l accumulation
    col_stats<<<BATCH * NH, 256>>>();
    attn_l_out<<<dim3(NLAN / 64, NH, BATCH), 256>>>();

    // 8-9: output projections straight into d_out
    gemm_tf32_bias<<<dim3(VD / 128, BATCH * NVIS / 128), 256>>>(Ov, Wv2o, bv2o, outv,
                                                                BATCH * NVIS, VD, EMB);
    gemm_tf32_bias<<<dim3(LD / 128, BATCH * NLAN / 128), 256>>>(Ol, Wl2o, bl2o, outl,
                                                                BATCH * NLAN, LD, EMB);
}